// round 15
// baseline (speedup 1.0000x reference)
#include <cuda_runtime.h>
#include <cuda_fp16.h>
#include <mma.h>
#include <math.h>
#include <cstdint>

using namespace nvcuda;

// Problem dims
#define BB 2
#define SS 4096
#define DD 768
#define HH 12
#define DHH 64
#define LL 12
#define FFF 3072
#define WW 256
#define ROWS (BB * SS)

typedef unsigned long long ull;

// -------- scratch (device globals; no allocation allowed) --------
__device__ float  g_x [ROWS * DD];          // fp32 residual stream
__device__ __half g_xh[ROWS * DD];          // fp16 copy for GEMM A
__device__ __half g_qh[ROWS * DD];
__device__ __half g_kh[ROWS * DD];
__device__ __half g_vh[ROWS * DD];
__device__ __half g_ch[ROWS * DD];          // attention context (fp16)
__device__ float  g_a0[ROWS * DD];          // split-K partial 0 (fp32)
__device__ float  g_a1[ROWS * DD];          // split-K partial 1 (fp32)
__device__ __half g_hh[ROWS * FFF];         // FFN hidden (fp16)
__device__ float  g_zero[FFF];              // zero bias (never written)
__device__ float  g_pp[BB * 16 * DD];
__device__ float  g_pooled[BB * DD];
__device__ float  g_h1[BB * 512];
// fp16 weights, SAME [K,N] layout (row_major wmma B needs no transpose)
__device__ __half g_wqh[LL * DD * DD];
__device__ __half g_wkh[LL * DD * DD];
__device__ __half g_wvh[LL * DD * DD];
__device__ __half g_woh[LL * DD * DD];
__device__ __half g_wih[LL * DD * FFF];
__device__ __half g_wfh[LL * FFF * DD];

// ---------------- cp.async ----------------
__device__ __forceinline__ void cp16(void* dst, const void* src) {
    unsigned int d = (unsigned int)__cvta_generic_to_shared(dst);
    asm volatile("cp.async.cg.shared.global [%0], [%1], 16;" :: "r"(d), "l"(src));
}
#define CP_COMMIT() asm volatile("cp.async.commit_group;")
#define CP_WAIT1()  asm volatile("cp.async.wait_group 1;")
#define CP_WAIT0()  asm volatile("cp.async.wait_group 0;")

// ---------------- misc ----------------
__device__ __forceinline__ float gelu_f(float x) {
    float x3 = x * x * x;
    float t = tanhf(0.7978845608028654f * (x + 0.044715f * x3));
    return 0.5f * x * (1.0f + t);
}
// 192-thread (6-warp) block reduce; red must hold >= 8 floats.
__device__ __forceinline__ float block_reduce_192(float v, float* red) {
    #pragma unroll
    for (int o = 16; o > 0; o >>= 1) v += __shfl_xor_sync(0xffffffffu, v, o);
    __syncthreads();
    if ((threadIdx.x & 31) == 0) red[threadIdx.x >> 5] = v;
    __syncthreads();
    if (threadIdx.x == 0) {
        float s = 0.f;
        #pragma unroll
        for (int i = 0; i < 6; i++) s += red[i];
        red[7] = s;
    }
    __syncthreads();
    return red[7];
}

// ---------------- weight fp32 -> fp16 convert ----------------
__global__ void convert_h_kernel(const float* __restrict__ src, __half* __restrict__ dst,
                                 int n4) {
    int i = blockIdx.x * blockDim.x + threadIdx.x;
    int stride = gridDim.x * blockDim.x;
    for (; i < n4; i += stride) {
        float4 v = ((const float4*)src)[i];
        ((__half2*)dst)[2 * i]     = __floats2half2_rn(v.x, v.y);
        ((__half2*)dst)[2 * i + 1] = __floats2half2_rn(v.z, v.w);
    }
}

// ---------------- embedding + LN (192 threads, float4 per thread) -----------
__global__ __launch_bounds__(192) void embed_ln_kernel(
    const int* __restrict__ tokens,
    const float* __restrict__ we, const float* __restrict__ pe,
    const float* __restrict__ te,
    const float* __restrict__ w, const float* __restrict__ b,
    float* __restrict__ x, __half* __restrict__ xh)
{
    __shared__ float red[8];
    int r = blockIdx.x;
    int ss = r % SS;
    int tok = tokens[r];
    int d4 = threadIdx.x * 4;
    size_t base = (size_t)r * DD;

    float4 wv = *(const float4*)(we + (size_t)tok * DD + d4);
    float4 pv = *(const float4*)(pe + (size_t)ss * DD + d4);
    float4 tv = *(const float4*)(te + d4);
    float f0 = wv.x + pv.x + tv.x;
    float f1 = wv.y + pv.y + tv.y;
    float f2 = wv.z + pv.z + tv.z;
    float f3 = wv.w + pv.w + tv.w;

    float mean = block_reduce_192(f0 + f1 + f2 + f3, red) * (1.0f / DD);
    float e0 = f0 - mean, e1 = f1 - mean, e2 = f2 - mean, e3 = f3 - mean;
    float var = block_reduce_192(e0 * e0 + e1 * e1 + e2 * e2 + e3 * e3, red) * (1.0f / DD);
    float rstd = rsqrtf(var + 1e-5f);

    float4 wt = *(const float4*)(w + d4);
    float4 bt = *(const float4*)(b + d4);
    float o0 = e0 * rstd * wt.x + bt.x;
    float o1 = e1 * rstd * wt.y + bt.y;
    float o2 = e2 * rstd * wt.z + bt.z;
    float o3 = e3 * rstd * wt.w + bt.w;
    *(float4*)(x + base + d4) = make_float4(o0, o1, o2, o3);
    __half2* xo = (__half2*)(xh + base + d4);
    xo[0] = __floats2half2_rn(o0, o1);
    xo[1] = __floats2half2_rn(o2, o3);
}

// ---------------- residual add (two partials) + LN ----------------
__global__ __launch_bounds__(192) void add_ln_kernel(
    float* __restrict__ x, const float* __restrict__ a0, const float* __restrict__ a1,
    const float* __restrict__ w, const float* __restrict__ b,
    __half* __restrict__ xh)
{
    __shared__ float red[8];
    int r = blockIdx.x;
    int d4 = threadIdx.x * 4;
    size_t base = (size_t)r * DD;

    float4 xv = *(const float4*)(x + base + d4);
    float4 v0 = *(const float4*)(a0 + base + d4);
    float4 v1 = *(const float4*)(a1 + base + d4);
    float f0 = xv.x + v0.x + v1.x;
    float f1 = xv.y + v0.y + v1.y;
    float f2 = xv.z + v0.z + v1.z;
    float f3 = xv.w + v0.w + v1.w;

    float mean = block_reduce_192(f0 + f1 + f2 + f3, red) * (1.0f / DD);
    float e0 = f0 - mean, e1 = f1 - mean, e2 = f2 - mean, e3 = f3 - mean;
    float var = block_reduce_192(e0 * e0 + e1 * e1 + e2 * e2 + e3 * e3, red) * (1.0f / DD);
    float rstd = rsqrtf(var + 1e-5f);

    float4 wt = *(const float4*)(w + d4);
    float4 bt = *(const float4*)(b + d4);
    float o0 = e0 * rstd * wt.x + bt.x;
    float o1 = e1 * rstd * wt.y + bt.y;
    float o2 = e2 * rstd * wt.z + bt.z;
    float o3 = e3 * rstd * wt.w + bt.w;
    *(float4*)(x + base + d4) = make_float4(o0, o1, o2, o3);
    __half2* xo = (__half2*)(xh + base + d4);
    xo[0] = __floats2half2_rn(o0, o1);
    xo[1] = __floats2half2_rn(o2, o3);
}

// ---------------- fp16 tensor-core GEMM (HMMA m16n16k16) --------------------
// CTA tile 256x128, 8 warps in 4(M) x 2(N), warp tile 64x64 (4x4 frags).
// BK=32, 3-stage cp.async, 1 CTA/SM. Per-z (B,bias,C,A-offset) for fused
// QKV (z=3) and split-K (z=2, partials summed in add_ln).
#define BM 256
#define BN 128
#define BK 32
#define STAGES 3
#define LDA_S 40
#define LDB_S 136
#define LDBIAS 132

#define SMEM_A_BYTES (STAGES * BM * LDA_S * 2)            // 61440
#define SMEM_B_BYTES (STAGES * BK * LDB_S * 2)            // 26112
#define SMEM_BIAS_BYTES (16 * LDBIAS * 4)                 //  8448
#define TGEMM_SMEM (SMEM_A_BYTES + SMEM_B_BYTES + SMEM_BIAS_BYTES)  // 96000

__global__ __launch_bounds__(256, 1) void hgemm_kernel(
    const __half* __restrict__ A, int ldA, int aoff1, int aoff2,
    const __half* __restrict__ B0, const __half* __restrict__ B1, const __half* __restrict__ B2,
    const float* __restrict__ bias0, const float* __restrict__ bias1, const float* __restrict__ bias2,
    void* C0, void* C1, void* C2,
    int M, int N, int Kloop, int mode)
{
    extern __shared__ char dynsmem[];
    __half (*As)[BM][LDA_S] = (__half (*)[BM][LDA_S])dynsmem;
    __half (*Bs)[BK][LDB_S] = (__half (*)[BK][LDB_S])(dynsmem + SMEM_A_BYTES);
    float  (*BiasT)[LDBIAS] = (float (*)[LDBIAS])(dynsmem + SMEM_A_BYTES + SMEM_B_BYTES);

    const __half* B;
    const float* bias;
    void* C;
    int aoff;
    if (blockIdx.z == 0)      { B = B0; bias = bias0; C = C0; aoff = 0; }
    else if (blockIdx.z == 1) { B = B1; bias = bias1; C = C1; aoff = aoff1; }
    else                      { B = B2; bias = bias2; C = C2; aoff = aoff2; }
    const __half* Az = A + aoff;

    int tid = threadIdx.x;
    int wid = tid >> 5;
    int bm = blockIdx.y * BM;
    int bn = blockIdx.x * BN;
    int warp_m = (wid & 3) * 64;
    int warp_n = (wid >> 2) * 64;

    auto load_tile = [&](int it, int buf) {
        int k0 = it * BK;
        // A: 256 rows x 32 halves = 1024 x 16B chunks, 4 per thread
        #pragma unroll
        for (int r = 0; r < 4; r++) {
            int e = tid + r * 256;
            int m = e >> 2, c8 = (e & 3) * 8;
            cp16(&As[buf][m][c8], Az + (size_t)(bm + m) * ldA + k0 + c8);
        }
        // B: 32 rows x 128 halves = 512 x 16B chunks, 2 per thread
        #pragma unroll
        for (int r = 0; r < 2; r++) {
            int e = tid + r * 256;
            int k = e >> 4, c8 = (e & 15) * 8;
            cp16(&Bs[buf][k][c8], B + (size_t)(k0 + k) * N + bn + c8);
        }
    };

    #pragma unroll
    for (int s = 0; s < STAGES - 1; s++) {
        load_tile(s, s);
        CP_COMMIT();
    }

    for (int e = tid; e < 16 * 128; e += 256) {
        int r = e >> 7, cn = e & 127;
        BiasT[r][cn] = bias[bn + cn];
    }
    __syncthreads();

    wmma::fragment<wmma::accumulator, 16, 16, 16, float> c[4][4];
    #pragma unroll
    for (int i = 0; i < 4; i++)
        #pragma unroll
        for (int j = 0; j < 4; j++)
            wmma::load_matrix_sync(c[i][j], &BiasT[0][warp_n + j * 16], LDBIAS,
                                   wmma::mem_row_major);

    int NT = Kloop / BK;
    int buf = 0;
    for (int it = 0; it < NT; it++) {
        CP_WAIT1();               // tile `it` ready (only tile it+1 may be pending)
        __syncthreads();

        #pragma unroll
        for (int ks = 0; ks < 2; ks++) {
            wmma::fragment<wmma::matrix_a, 16, 16, 16, __half, wmma::row_major> a[4];
            wmma::fragment<wmma::matrix_b, 16, 16, 16, __half, wmma::row_major> b[4];
            #pragma unroll
            for (int i = 0; i < 4; i++)
                wmma::load_matrix_sync(a[i], &As[buf][warp_m + i * 16][ks * 16], LDA_S);
            #pragma unroll
            for (int j = 0; j < 4; j++)
                wmma::load_matrix_sync(b[j], &Bs[buf][ks * 16][warp_n + j * 16], LDB_S);
            #pragma unroll
            for (int i = 0; i < 4; i++)
                #pragma unroll
                for (int j = 0; j < 4; j++)
                    wmma::mma_sync(c[i][j], a[i], b[j], c[i][j]);
        }

        // always commit (possibly-empty group) to keep wait_group counting uniform
        int nt = it + STAGES - 1;
        int nbuf = buf + STAGES - 1;
        if (nbuf >= STAGES) nbuf -= STAGES;
        if (nt < NT) load_tile(nt, nbuf);
        CP_COMMIT();
        if (++buf == STAGES) buf = 0;
    }

    if (mode == 0) {
        float* Cf = (float*)C;
        #pragma unroll
        for (int i = 0; i < 4; i++)
            #pragma unroll
            for (int j = 0; j < 4; j++) {
                float* Cp = Cf + (size_t)(bm + warp_m + i * 16) * N + bn + warp_n + j * 16;
                wmma::store_matrix_sync(Cp, c[i][j], N, wmma::mem_row_major);
            }
    } else {
        __half* Ch = (__half*)C;
        #pragma unroll
        for (int i = 0; i < 4; i++)
            #pragma unroll
            for (int j = 0; j < 4; j++) {
                wmma::fragment<wmma::accumulator, 16, 16, 16, __half> chf;
                #pragma unroll
                for (int t = 0; t < chf.num_elements; t++) {
                    float v = c[i][j].x[t];
                    if (mode == 2) v = gelu_f(v);
                    chf.x[t] = __float2half(v);
                }
                __half* Cp = Ch + (size_t)(bm + warp_m + i * 16) * N + bn + warp_n + j * 16;
                wmma::store_matrix_sync(Cp, chf, N, wmma::mem_row_major);
            }
    }
}

// ---------------- tensor-core local attention ----------------
#define ATT_Q_OFF 0
#define ATT_K_OFF 18432
#define ATT_V_OFF 27648
#define ATT_P_OFF 36864
#define ATT_S_OFF 55296
#define ATT_M_OFF 92160
#define ATT_SMEM  92416

__global__ __launch_bounds__(256, 2) void attn_wmma_kernel(
    const __half* __restrict__ Q, const __half* __restrict__ K,
    const __half* __restrict__ V, const int* __restrict__ mask,
    __half* __restrict__ O)
{
    extern __shared__ char sm[];
    __half* Qs = (__half*)(sm + ATT_Q_OFF);
    __half* Ks = (__half*)(sm + ATT_K_OFF);
    __half* Vs = (__half*)(sm + ATT_V_OFF);
    __half* Ps = (__half*)(sm + ATT_P_OFF);
    float*  Ss = (float*)(sm + ATT_S_OFF);
    int*    Ms = (int*)(sm + ATT_M_OFF);

    int h = blockIdx.y, b = blockIdx.z;
    int tid = threadIdx.x, wid = tid >> 5;
    int q0 = blockIdx.x * 128;
    size_t bS = (size_t)b * SS;

    for (int e = tid; e < 128 * 8; e += 256) {
        int r = e >> 3, c16 = e & 7;
        cp16(Qs + r * 72 + c16 * 8, Q + (bS + q0 + r) * DD + h * DHH + c16 * 8);
    }
    CP_COMMIT();

    float lsum = 0.f;
    int sr = tid >> 1;
    int sc0 = (tid & 1) * 32;

    wmma::fragment<wmma::accumulator, 16, 16, 16, float> co[4];
    #pragma unroll
    for (int j = 0; j < 4; j++) wmma::fill_fragment(co[j], 0.f);

    for (int t = 0; t < 10; t++) {
        __syncthreads();
        int kbase = q0 - 256 + t * 64;
        #pragma unroll
        for (int rr = 0; rr < 2; rr++) {
            int e = tid + rr * 256;
            int row = e >> 3, c16 = e & 7;
            int p = kbase + row;
            if ((unsigned)p < SS) {
                size_t off = (bS + p) * DD + h * DHH + c16 * 8;
                cp16(Ks + row * 72 + c16 * 8, K + off);
                cp16(Vs + row * 72 + c16 * 8, V + off);
            } else {
                *(uint4*)(Ks + row * 72 + c16 * 8) = make_uint4(0, 0, 0, 0);
                *(uint4*)(Vs + row * 72 + c16 * 8) = make_uint4(0, 0, 0, 0);
            }
        }
        if (tid < 64) {
            int p = kbase + tid;
            Ms[tid] = ((unsigned)p < SS) ? mask[b * SS + p] : 0;
        }
        CP_COMMIT();
        CP_WAIT0();
        __syncthreads();

        bool active = (64 * t + 63 >= 16 * wid) && (64 * t <= 527 + 16 * wid);

        if (active) {
            wmma::fragment<wmma::accumulator, 16, 16, 16, float> cs[4];
            #pragma unroll
            for (int j = 0; j < 4; j++) wmma::fill_fragment(cs[j], 0.f);
            #pragma unroll
            for (int kk = 0; kk < 4; kk++) {
                wmma::fragment<wmma::matrix_a, 16, 16, 16, __half, wmma::row_major> a;
                wmma::load_matrix_sync(a, Qs + (16 * wid) * 72 + 16 * kk, 72);
                #pragma unroll
                for (int j = 0; j < 4; j++) {
                    wmma::fragment<wmma::matrix_b, 16, 16, 16, __half, wmma::col_major> bt;
                    wmma::load_matrix_sync(bt, Ks + (16 * j) * 72 + 16 * kk, 72);
                    wmma::mma_sync(cs[j], a, bt, cs[j]);
                }
            }
            #pragma unroll
            for (int j = 0; j < 4; j++)
                wmma::store_matrix_sync(Ss + (16 * wid) * 72 + 16 * j, cs[j], 72,
                                        wmma::mem_row_major);
        }
        __syncthreads();

        if (active) {
            #pragma unroll
            for (int k = 0; k < 32; k++) {
                int col = sc0 + k;
                int d = 64 * t + col - sr;
                float pv = 0.f;
                if (d >= 0 && d <= 512 && Ms[col])
                    pv = __expf(Ss[sr * 72 + col] * 0.125f);
                Ps[sr * 72 + col] = __float2half(pv);
                lsum += pv;
            }
        }
        __syncthreads();

        if (active) {
            #pragma unroll
            for (int kk = 0; kk < 4; kk++) {
                wmma::fragment<wmma::matrix_a, 16, 16, 16, __half, wmma::row_major> a;
                wmma::load_matrix_sync(a, Ps + (16 * wid) * 72 + 16 * kk, 72);
                #pragma unroll
                for (int j = 0; j < 4; j++) {
                    wmma::fragment<wmma::matrix_b, 16, 16, 16, __half, wmma::row_major> bt;
                    wmma::load_matrix_sync(bt, Vs + (16 * kk) * 72 + 16 * j, 72);
                    wmma::mma_sync(co[j], a, bt, co[j]);
                }
            }
        }
    }

    __syncthreads();
    #pragma unroll
    for (int j = 0; j < 4; j++)
        wmma::store_matrix_sync(Ss + (16 * wid) * 72 + 16 * j, co[j], 72,
                                wmma::mem_row_major);
    __syncthreads();

    float ltot = lsum + __shfl_xor_sync(0xffffffff, lsum, 1);
    float inv = 1.0f / ltot;
    __half2* op = (__half2*)(O + (bS + q0 + sr) * DD + h * DHH + sc0);
    #pragma unroll
    for (int k = 0; k < 32; k += 2) {
        float v0 = Ss[sr * 72 + sc0 + k] * inv;
        float v1 = Ss[sr * 72 + sc0 + k + 1] * inv;
        op[k >> 1] = __floats2half2_rn(v0, v1);
    }
}

// ---------------- mean pool ----------------
__global__ void pool_partial_kernel(const float* __restrict__ x, float* __restrict__ pp) {
    int b = blockIdx.x;
    int chunk = blockIdx.y;
    int d = threadIdx.x;
    float s = 0.f;
    for (int s0 = 0; s0 < 256; s0++) {
        int srow = chunk * 256 + s0;
        s += x[((size_t)(b * SS + srow)) * DD + d];
    }
    pp[(b * 16 + chunk) * DD + d] = s;
}
__global__ void pool_final_kernel(const float* __restrict__ pp, float* __restrict__ pooled) {
    int b = blockIdx.x;
    int d = threadIdx.x;
    float s = 0.f;
    #pragma unroll
    for (int c = 0; c < 16; c++) s += pp[(b * 16 + c) * DD + d];
    pooled[b * DD + d] = s * (1.0f / SS);
}

// ---------------- projection head ----------------
__global__ void head1_kernel(const float* __restrict__ pooled,
                             const float* __restrict__ w, const float* __restrict__ bias,
                             float* __restrict__ h1) {
    int m = blockIdx.y;
    int n = blockIdx.x * 256 + threadIdx.x;
    float s = bias[n];
    for (int k = 0; k < DD; k++) s += pooled[m * DD + k] * w[k * 512 + n];
    const float alpha = 1.6732632423543772f;
    const float scale = 1.0507009873554805f;
    h1[m * 512 + n] = (s > 0.f) ? scale * s : scale * alpha * expm1f(s);
}
__global__ void head2_kernel(const float* __restrict__ h1,
                             const float* __restrict__ w, const float* __restrict__ bias,
                             float* __restrict__ out) {
    int m = blockIdx.y;
    int n = threadIdx.x;
    float s = bias[n];
    for (int k = 0; k < 512; k++) s += h1[m * 512 + k] * w[k * 256 + n];
    out[m * 256 + n] = s;
}

// ---------------- launch ----------------
extern "C" void kernel_launch(void* const* d_in, const int* in_sizes, int n_in,
                              void* d_out, int out_size) {
    const int*   tokens = (const int*)  d_in[0];
    const int*   amask  = (const int*)  d_in[1];
    const float* we     = (const float*)d_in[2];
    const float* pe     = (const float*)d_in[3];
    const float* te     = (const float*)d_in[4];
    const float* ln_e_w = (const float*)d_in[5];
    const float* ln_e_b = (const float*)d_in[6];
    const float* Wq     = (const float*)d_in[7];
    const float* bq     = (const float*)d_in[8];
    const float* Wk     = (const float*)d_in[9];
    const float* bk     = (const float*)d_in[10];
    const float* Wv     = (const float*)d_in[11];
    const float* bv     = (const float*)d_in[12];
    const float* Wo     = (const float*)d_in[13];
    const float* bo     = (const float*)d_in[14];
    const float* ln1_w  = (const float*)d_in[15];
    const float* ln1_b  = (const float*)d_in[16];
    const float* Wi     = (const float*)d_in[17];
    const float* bi     = (const float*)d_in[18];
    const float* Wf     = (const float*)d_in[19];
    const float* bf     = (const float*)d_in[20];
    const float* ln2_w  = (const float*)d_in[21];
    const float* ln2_b  = (const float*)d_in[22];
    const float* p1_w   = (const float*)d_in[23];
    const float* p1_b   = (const float*)d_in[24];
    const float* p2_w   = (const float*)d_in[25];
    const float* p2_b   = (const float*)d_in[26];
    float* out = (float*)d_out;

    float  *px, *pa0, *pa1, *pz, *ppp, *ppool, *ph1;
    __half *pxh, *pqh, *pkh, *pvh, *pch, *phh;
    __half *pwq, *pwk, *pwv, *pwo, *pwi, *pwf;
    cudaGetSymbolAddress((void**)&px, g_x);
    cudaGetSymbolAddress((void**)&pxh, g_xh);
    cudaGetSymbolAddress((void**)&pqh, g_qh);
    cudaGetSymbolAddress((void**)&pkh, g_kh);
    cudaGetSymbolAddress((void**)&pvh, g_vh);
    cudaGetSymbolAddress((void**)&pch, g_ch);
    cudaGetSymbolAddress((void**)&pa0, g_a0);
    cudaGetSymbolAddress((void**)&pa1, g_a1);
    cudaGetSymbolAddress((void**)&pz, g_zero);
    cudaGetSymbolAddress((void**)&phh, g_hh);
    cudaGetSymbolAddress((void**)&ppp, g_pp);
    cudaGetSymbolAddress((void**)&ppool, g_pooled);
    cudaGetSymbolAddress((void**)&ph1, g_h1);
    cudaGetSymbolAddress((void**)&pwq, g_wqh);
    cudaGetSymbolAddress((void**)&pwk, g_wkh);
    cudaGetSymbolAddress((void**)&pwv, g_wvh);
    cudaGetSymbolAddress((void**)&pwo, g_woh);
    cudaGetSymbolAddress((void**)&pwi, g_wih);
    cudaGetSymbolAddress((void**)&pwf, g_wfh);

    cudaFuncSetAttribute(hgemm_kernel,
                         cudaFuncAttributeMaxDynamicSharedMemorySize, TGEMM_SMEM);
    cudaFuncSetAttribute(attn_wmma_kernel,
                         cudaFuncAttributeMaxDynamicSharedMemorySize, ATT_SMEM);

    {
        const int nQ = LL * DD * DD / 4;
        const int nF = LL * DD * FFF / 4;
        convert_h_kernel<<<2048, 256>>>(Wq, pwq, nQ);
        convert_h_kernel<<<2048, 256>>>(Wk, pwk, nQ);
        convert_h_kernel<<<2048, 256>>>(Wv, pwv, nQ);
        convert_h_kernel<<<2048, 256>>>(Wo, pwo, nQ);
        convert_h_kernel<<<4096, 256>>>(Wi, pwi, nF);
        convert_h_kernel<<<4096, 256>>>(Wf, pwf, nF);
    }

    embed_ln_kernel<<<ROWS, 192>>>(tokens, we, pe, te, ln_e_w, ln_e_b, px, pxh);

    dim3 gQKV(DD / 128, ROWS / 256, 3);      // 576 blocks
    dim3 gSplit(DD / 128, ROWS / 256, 2);    // 384 blocks (split-K O / FF2)
    dim3 gFF1(FFF / 128, ROWS / 256, 1);     // 768 blocks
    dim3 gAttn(SS / 128, HH, BB);            // 768 blocks

    for (int l = 0; l < LL; l++) {
        const __half* wq = pwq + (size_t)l * DD * DD;
        const __half* wk = pwk + (size_t)l * DD * DD;
        const __half* wv = pwv + (size_t)l * DD * DD;
        const __half* wo = pwo + (size_t)l * DD * DD;
        const __half* wi = pwi + (size_t)l * DD * FFF;
        const __half* wf = pwf + (size_t)l * FFF * DD;

        // fused QKV: full K, no A offset
        hgemm_kernel<<<gQKV, 256, TGEMM_SMEM>>>(
            pxh, DD, 0, 0, wq, wk, wv,
            bq + l * DD, bk + l * DD, bv + l * DD,
            pqh, pkh, pvh, ROWS, DD, DD, 1);

        attn_wmma_kernel<<<gAttn, 256, ATT_SMEM>>>(pqh, pkh, pvh, amask, pch);

        // O projection, split-K2
        hgemm_kernel<<<gSplit, 256, TGEMM_SMEM>>>(
            pch, DD, 384, 0, wo, wo + (size_t)384 * DD, wo,
            bo + l * DD, pz, pz,
            pa0, pa1, pa0, ROWS, DD, 384, 0);
        add_ln_kernel<<<ROWS, 192>>>(px, pa0, pa1, ln1_w + l * DD, ln1_b + l * DD, pxh);

        hgemm_kernel<<<gFF1, 256, TGEMM_SMEM>>>(
            pxh, DD, 0, 0, wi, wi, wi,
            bi + l * FFF, bi + l * FFF, bi + l * FFF,
            phh, phh, phh, ROWS, FFF, DD, 2);

        // FF2, split-K2
        hgemm_kernel<<<gSplit, 256, TGEMM_SMEM>>>(
            phh, FFF, 1536, 0, wf, wf + (size_t)1536 * DD, wf,
            bf + l * DD, pz, pz,
            pa0, pa1, pa0, ROWS, DD, 1536, 0);
        add_ln_kernel<<<ROWS, 192>>>(px, pa0, pa1, ln2_w + l * DD, ln2_b + l * DD, pxh);
    }

    pool_partial_kernel<<<dim3(BB, 16), DD>>>(px, ppp);
    pool_final_kernel<<<BB, DD>>>(ppp, ppool);
    head1_kernel<<<dim3(2, BB), 256>>>(ppool, p1_w, p1_b, ph1);
    head2_kernel<<<dim3(1, BB), 256>>>(ph1, p2_w, p2_b, out);
}

// round 16
// speedup vs baseline: 1.0273x; 1.0273x over previous
#include <cuda_runtime.h>
#include <cuda_fp16.h>
#include <mma.h>
#include <math.h>
#include <cstdint>

using namespace nvcuda;

// Problem dims
#define BB 2
#define SS 4096
#define DD 768
#define HH 12
#define DHH 64
#define LL 12
#define FFF 3072
#define WW 256
#define ROWS (BB * SS)

typedef unsigned long long ull;

// -------- scratch (device globals; no allocation allowed) --------
__device__ float  g_x [ROWS * DD];          // fp32 residual stream
__device__ __half g_xh[ROWS * DD];          // fp16 copy for GEMM A
__device__ __half g_qh[ROWS * DD];
__device__ __half g_kh[ROWS * DD];
__device__ __half g_vh[ROWS * DD];
__device__ __half g_ch[ROWS * DD];          // attention context (fp16)
__device__ float  g_a0[ROWS * DD];          // split-K partial 0 (fp32)
__device__ float  g_a1[ROWS * DD];          // split-K partial 1 (fp32)
__device__ __half g_hh[ROWS * FFF];         // FFN hidden (fp16)
__device__ float  g_zero[FFF];              // zero bias (never written)
__device__ float  g_pp[BB * 16 * DD];
__device__ float  g_pooled[BB * DD];
__device__ float  g_h1[BB * 512];
// fp16 weights, SAME [K,N] layout (row_major wmma B needs no transpose)
__device__ __half g_wqh[LL * DD * DD];
__device__ __half g_wkh[LL * DD * DD];
__device__ __half g_wvh[LL * DD * DD];
__device__ __half g_woh[LL * DD * DD];
__device__ __half g_wih[LL * DD * FFF];
__device__ __half g_wfh[LL * FFF * DD];

// ---------------- cp.async ----------------
__device__ __forceinline__ void cp16(void* dst, const void* src) {
    unsigned int d = (unsigned int)__cvta_generic_to_shared(dst);
    asm volatile("cp.async.cg.shared.global [%0], [%1], 16;" :: "r"(d), "l"(src));
}
#define CP_COMMIT() asm volatile("cp.async.commit_group;")
#define CP_WAIT0()  asm volatile("cp.async.wait_group 0;")

// ---------------- misc ----------------
__device__ __forceinline__ float gelu_f(float x) {
    float x3 = x * x * x;
    float t = tanhf(0.7978845608028654f * (x + 0.044715f * x3));
    return 0.5f * x * (1.0f + t);
}
// 192-thread (6-warp) block reduce; red must hold >= 8 floats.
__device__ __forceinline__ float block_reduce_192(float v, float* red) {
    #pragma unroll
    for (int o = 16; o > 0; o >>= 1) v += __shfl_xor_sync(0xffffffffu, v, o);
    __syncthreads();
    if ((threadIdx.x & 31) == 0) red[threadIdx.x >> 5] = v;
    __syncthreads();
    if (threadIdx.x == 0) {
        float s = 0.f;
        #pragma unroll
        for (int i = 0; i < 6; i++) s += red[i];
        red[7] = s;
    }
    __syncthreads();
    return red[7];
}

// ---------------- weight fp32 -> fp16 convert ----------------
__global__ void convert_h_kernel(const float* __restrict__ src, __half* __restrict__ dst,
                                 int n4) {
    int i = blockIdx.x * blockDim.x + threadIdx.x;
    int stride = gridDim.x * blockDim.x;
    for (; i < n4; i += stride) {
        float4 v = ((const float4*)src)[i];
        ((__half2*)dst)[2 * i]     = __floats2half2_rn(v.x, v.y);
        ((__half2*)dst)[2 * i + 1] = __floats2half2_rn(v.z, v.w);
    }
}

// ---------------- embedding + LN (192 threads, float4 per thread) -----------
__global__ __launch_bounds__(192) void embed_ln_kernel(
    const int* __restrict__ tokens,
    const float* __restrict__ we, const float* __restrict__ pe,
    const float* __restrict__ te,
    const float* __restrict__ w, const float* __restrict__ b,
    float* __restrict__ x, __half* __restrict__ xh)
{
    __shared__ float red[8];
    int r = blockIdx.x;
    int ss = r % SS;
    int tok = tokens[r];
    int d4 = threadIdx.x * 4;
    size_t base = (size_t)r * DD;

    float4 wv = *(const float4*)(we + (size_t)tok * DD + d4);
    float4 pv = *(const float4*)(pe + (size_t)ss * DD + d4);
    float4 tv = *(const float4*)(te + d4);
    float f0 = wv.x + pv.x + tv.x;
    float f1 = wv.y + pv.y + tv.y;
    float f2 = wv.z + pv.z + tv.z;
    float f3 = wv.w + pv.w + tv.w;

    float mean = block_reduce_192(f0 + f1 + f2 + f3, red) * (1.0f / DD);
    float e0 = f0 - mean, e1 = f1 - mean, e2 = f2 - mean, e3 = f3 - mean;
    float var = block_reduce_192(e0 * e0 + e1 * e1 + e2 * e2 + e3 * e3, red) * (1.0f / DD);
    float rstd = rsqrtf(var + 1e-5f);

    float4 wt = *(const float4*)(w + d4);
    float4 bt = *(const float4*)(b + d4);
    float o0 = e0 * rstd * wt.x + bt.x;
    float o1 = e1 * rstd * wt.y + bt.y;
    float o2 = e2 * rstd * wt.z + bt.z;
    float o3 = e3 * rstd * wt.w + bt.w;
    *(float4*)(x + base + d4) = make_float4(o0, o1, o2, o3);
    __half2* xo = (__half2*)(xh + base + d4);
    xo[0] = __floats2half2_rn(o0, o1);
    xo[1] = __floats2half2_rn(o2, o3);
}

// ---------------- residual add (two partials) + LN ----------------
__global__ __launch_bounds__(192) void add_ln_kernel(
    float* __restrict__ x, const float* __restrict__ a0, const float* __restrict__ a1,
    const float* __restrict__ w, const float* __restrict__ b,
    __half* __restrict__ xh)
{
    __shared__ float red[8];
    int r = blockIdx.x;
    int d4 = threadIdx.x * 4;
    size_t base = (size_t)r * DD;

    float4 xv = *(const float4*)(x + base + d4);
    float4 v0 = *(const float4*)(a0 + base + d4);
    float4 v1 = *(const float4*)(a1 + base + d4);
    float f0 = xv.x + v0.x + v1.x;
    float f1 = xv.y + v0.y + v1.y;
    float f2 = xv.z + v0.z + v1.z;
    float f3 = xv.w + v0.w + v1.w;

    float mean = block_reduce_192(f0 + f1 + f2 + f3, red) * (1.0f / DD);
    float e0 = f0 - mean, e1 = f1 - mean, e2 = f2 - mean, e3 = f3 - mean;
    float var = block_reduce_192(e0 * e0 + e1 * e1 + e2 * e2 + e3 * e3, red) * (1.0f / DD);
    float rstd = rsqrtf(var + 1e-5f);

    float4 wt = *(const float4*)(w + d4);
    float4 bt = *(const float4*)(b + d4);
    float o0 = e0 * rstd * wt.x + bt.x;
    float o1 = e1 * rstd * wt.y + bt.y;
    float o2 = e2 * rstd * wt.z + bt.z;
    float o3 = e3 * rstd * wt.w + bt.w;
    *(float4*)(x + base + d4) = make_float4(o0, o1, o2, o3);
    __half2* xo = (__half2*)(xh + base + d4);
    xo[0] = __floats2half2_rn(o0, o1);
    xo[1] = __floats2half2_rn(o2, o3);
}

// ---------------- fp16 tensor-core GEMM (HMMA m16n16k16) --------------------
// CTA tile 128x128, 8 warps 4(M)x2(N), warp tile 32x64 (2x4 frags).
// BK=64, 2-stage double buffer (half the barriers of BK=32), 2 CTAs/SM.
// Per-z (B,bias,C,A-offset): fused QKV (z=3), split-K (z=2).
#define BM 128
#define BN 128
#define BK 64
#define LDA_S 72     // halves: BK + 8 pad (144 B rows, 16B aligned)
#define LDB_S 136    // halves: BN + 8 pad
#define LDBIAS 132

#define SMEM_A_BYTES (2 * BM * LDA_S * 2)                 // 36864
#define SMEM_B_BYTES (2 * BK * LDB_S * 2)                 // 34816
#define SMEM_BIAS_BYTES (16 * LDBIAS * 4)                 //  8448
#define TGEMM_SMEM (SMEM_A_BYTES + SMEM_B_BYTES + SMEM_BIAS_BYTES)  // 80128

__global__ __launch_bounds__(256, 2) void hgemm_kernel(
    const __half* __restrict__ A, int ldA, int aoff1, int aoff2,
    const __half* __restrict__ B0, const __half* __restrict__ B1, const __half* __restrict__ B2,
    const float* __restrict__ bias0, const float* __restrict__ bias1, const float* __restrict__ bias2,
    void* C0, void* C1, void* C2,
    int M, int N, int Kloop, int mode)
{
    extern __shared__ char dynsmem[];
    __half (*As)[BM][LDA_S] = (__half (*)[BM][LDA_S])dynsmem;
    __half (*Bs)[BK][LDB_S] = (__half (*)[BK][LDB_S])(dynsmem + SMEM_A_BYTES);
    float  (*BiasT)[LDBIAS] = (float (*)[LDBIAS])(dynsmem + SMEM_A_BYTES + SMEM_B_BYTES);

    const __half* B;
    const float* bias;
    void* C;
    int aoff;
    if (blockIdx.z == 0)      { B = B0; bias = bias0; C = C0; aoff = 0; }
    else if (blockIdx.z == 1) { B = B1; bias = bias1; C = C1; aoff = aoff1; }
    else                      { B = B2; bias = bias2; C = C2; aoff = aoff2; }
    const __half* Az = A + aoff;

    int tid = threadIdx.x;
    int wid = tid >> 5;
    int bm = blockIdx.y * BM;
    int bn = blockIdx.x * BN;
    int warp_m = (wid & 3) * 32;
    int warp_n = (wid >> 2) * 64;

    auto load_tile = [&](int it, int buf) {
        int k0 = it * BK;
        // A: 128 rows x 64 halves (128 B/row) = 1024 x 16B chunks, 4/thread
        #pragma unroll
        for (int r = 0; r < 4; r++) {
            int e = tid + r * 256;
            int m = e >> 3, c8 = (e & 7) * 8;
            cp16(&As[buf][m][c8], Az + (size_t)(bm + m) * ldA + k0 + c8);
        }
        // B: 64 rows x 128 halves (256 B/row) = 1024 x 16B chunks, 4/thread
        #pragma unroll
        for (int r = 0; r < 4; r++) {
            int e = tid + r * 256;
            int k = e >> 4, c8 = (e & 15) * 8;
            cp16(&Bs[buf][k][c8], B + (size_t)(k0 + k) * N + bn + c8);
        }
    };

    load_tile(0, 0);
    CP_COMMIT();

    for (int e = tid; e < 16 * 128; e += 256) {
        int r = e >> 7, cn = e & 127;
        BiasT[r][cn] = bias[bn + cn];
    }
    __syncthreads();

    wmma::fragment<wmma::accumulator, 16, 16, 16, float> c[2][4];
    #pragma unroll
    for (int i = 0; i < 2; i++)
        #pragma unroll
        for (int j = 0; j < 4; j++)
            wmma::load_matrix_sync(c[i][j], &BiasT[0][warp_n + j * 16], LDBIAS,
                                   wmma::mem_row_major);

    int NT = Kloop / BK;
    for (int it = 0; it < NT; it++) {
        int buf = it & 1;
        CP_WAIT0();               // tile `it` resident
        __syncthreads();

        // issue next tile load BEFORE compute so it overlaps the 4 ks-steps
        if (it + 1 < NT) load_tile(it + 1, buf ^ 1);
        CP_COMMIT();

        #pragma unroll
        for (int ks = 0; ks < 4; ks++) {
            wmma::fragment<wmma::matrix_a, 16, 16, 16, __half, wmma::row_major> a[2];
            wmma::fragment<wmma::matrix_b, 16, 16, 16, __half, wmma::row_major> b[4];
            #pragma unroll
            for (int i = 0; i < 2; i++)
                wmma::load_matrix_sync(a[i], &As[buf][warp_m + i * 16][ks * 16], LDA_S);
            #pragma unroll
            for (int j = 0; j < 4; j++)
                wmma::load_matrix_sync(b[j], &Bs[buf][ks * 16][warp_n + j * 16], LDB_S);
            #pragma unroll
            for (int i = 0; i < 2; i++)
                #pragma unroll
                for (int j = 0; j < 4; j++)
                    wmma::mma_sync(c[i][j], a[i], b[j], c[i][j]);
        }
    }

    if (mode == 0) {
        float* Cf = (float*)C;
        #pragma unroll
        for (int i = 0; i < 2; i++)
            #pragma unroll
            for (int j = 0; j < 4; j++) {
                float* Cp = Cf + (size_t)(bm + warp_m + i * 16) * N + bn + warp_n + j * 16;
                wmma::store_matrix_sync(Cp, c[i][j], N, wmma::mem_row_major);
            }
    } else {
        __half* Ch = (__half*)C;
        #pragma unroll
        for (int i = 0; i < 2; i++)
            #pragma unroll
            for (int j = 0; j < 4; j++) {
                wmma::fragment<wmma::accumulator, 16, 16, 16, __half> chf;
                #pragma unroll
                for (int t = 0; t < chf.num_elements; t++) {
                    float v = c[i][j].x[t];
                    if (mode == 2) v = gelu_f(v);
                    chf.x[t] = __float2half(v);
                }
                __half* Cp = Ch + (size_t)(bm + warp_m + i * 16) * N + bn + warp_n + j * 16;
                wmma::store_matrix_sync(Cp, chf, N, wmma::mem_row_major);
            }
    }
}

// ---------------- tensor-core local attention ----------------
#define ATT_Q_OFF 0
#define ATT_K_OFF 18432
#define ATT_V_OFF 27648
#define ATT_P_OFF 36864
#define ATT_S_OFF 55296
#define ATT_M_OFF 92160
#define ATT_SMEM  92416

__global__ __launch_bounds__(256, 2) void attn_wmma_kernel(
    const __half* __restrict__ Q, const __half* __restrict__ K,
    const __half* __restrict__ V, const int* __restrict__ mask,
    __half* __restrict__ O)
{
    extern __shared__ char sm[];
    __half* Qs = (__half*)(sm + ATT_Q_OFF);
    __half* Ks = (__half*)(sm + ATT_K_OFF);
    __half* Vs = (__half*)(sm + ATT_V_OFF);
    __half* Ps = (__half*)(sm + ATT_P_OFF);
    float*  Ss = (float*)(sm + ATT_S_OFF);
    int*    Ms = (int*)(sm + ATT_M_OFF);

    int h = blockIdx.y, b = blockIdx.z;
    int tid = threadIdx.x, wid = tid >> 5;
    int q0 = blockIdx.x * 128;
    size_t bS = (size_t)b * SS;

    for (int e = tid; e < 128 * 8; e += 256) {
        int r = e >> 3, c16 = e & 7;
        cp16(Qs + r * 72 + c16 * 8, Q + (bS + q0 + r) * DD + h * DHH + c16 * 8);
    }
    CP_COMMIT();

    float lsum = 0.f;
    int sr = tid >> 1;
    int sc0 = (tid & 1) * 32;

    wmma::fragment<wmma::accumulator, 16, 16, 16, float> co[4];
    #pragma unroll
    for (int j = 0; j < 4; j++) wmma::fill_fragment(co[j], 0.f);

    for (int t = 0; t < 10; t++) {
        __syncthreads();
        int kbase = q0 - 256 + t * 64;
        #pragma unroll
        for (int rr = 0; rr < 2; rr++) {
            int e = tid + rr * 256;
            int row = e >> 3, c16 = e & 7;
            int p = kbase + row;
            if ((unsigned)p < SS) {
                size_t off = (bS + p) * DD + h * DHH + c16 * 8;
                cp16(Ks + row * 72 + c16 * 8, K + off);
                cp16(Vs + row * 72 + c16 * 8, V + off);
            } else {
                *(uint4*)(Ks + row * 72 + c16 * 8) = make_uint4(0, 0, 0, 0);
                *(uint4*)(Vs + row * 72 + c16 * 8) = make_uint4(0, 0, 0, 0);
            }
        }
        if (tid < 64) {
            int p = kbase + tid;
            Ms[tid] = ((unsigned)p < SS) ? mask[b * SS + p] : 0;
        }
        CP_COMMIT();
        CP_WAIT0();
        __syncthreads();

        bool active = (64 * t + 63 >= 16 * wid) && (64 * t <= 527 + 16 * wid);

        if (active) {
            wmma::fragment<wmma::accumulator, 16, 16, 16, float> cs[4];
            #pragma unroll
            for (int j = 0; j < 4; j++) wmma::fill_fragment(cs[j], 0.f);
            #pragma unroll
            for (int kk = 0; kk < 4; kk++) {
                wmma::fragment<wmma::matrix_a, 16, 16, 16, __half, wmma::row_major> a;
                wmma::load_matrix_sync(a, Qs + (16 * wid) * 72 + 16 * kk, 72);
                #pragma unroll
                for (int j = 0; j < 4; j++) {
                    wmma::fragment<wmma::matrix_b, 16, 16, 16, __half, wmma::col_major> bt;
                    wmma::load_matrix_sync(bt, Ks + (16 * j) * 72 + 16 * kk, 72);
                    wmma::mma_sync(cs[j], a, bt, cs[j]);
                }
            }
            #pragma unroll
            for (int j = 0; j < 4; j++)
                wmma::store_matrix_sync(Ss + (16 * wid) * 72 + 16 * j, cs[j], 72,
                                        wmma::mem_row_major);
        }
        __syncthreads();

        if (active) {
            #pragma unroll
            for (int k = 0; k < 32; k++) {
                int col = sc0 + k;
                int d = 64 * t + col - sr;
                float pv = 0.f;
                if (d >= 0 && d <= 512 && Ms[col])
                    pv = __expf(Ss[sr * 72 + col] * 0.125f);
                Ps[sr * 72 + col] = __float2half(pv);
                lsum += pv;
            }
        }
        __syncthreads();

        if (active) {
            #pragma unroll
            for (int kk = 0; kk < 4; kk++) {
                wmma::fragment<wmma::matrix_a, 16, 16, 16, __half, wmma::row_major> a;
                wmma::load_matrix_sync(a, Ps + (16 * wid) * 72 + 16 * kk, 72);
                #pragma unroll
                for (int j = 0; j < 4; j++) {
                    wmma::fragment<wmma::matrix_b, 16, 16, 16, __half, wmma::row_major> bt;
                    wmma::load_matrix_sync(bt, Vs + (16 * kk) * 72 + 16 * j, 72);
                    wmma::mma_sync(co[j], a, bt, co[j]);
                }
            }
        }
    }

    __syncthreads();
    #pragma unroll
    for (int j = 0; j < 4; j++)
        wmma::store_matrix_sync(Ss + (16 * wid) * 72 + 16 * j, co[j], 72,
                                wmma::mem_row_major);
    __syncthreads();

    float ltot = lsum + __shfl_xor_sync(0xffffffff, lsum, 1);
    float inv = 1.0f / ltot;
    __half2* op = (__half2*)(O + (bS + q0 + sr) * DD + h * DHH + sc0);
    #pragma unroll
    for (int k = 0; k < 32; k += 2) {
        float v0 = Ss[sr * 72 + sc0 + k] * inv;
        float v1 = Ss[sr * 72 + sc0 + k + 1] * inv;
        op[k >> 1] = __floats2half2_rn(v0, v1);
    }
}

// ---------------- mean pool ----------------
__global__ void pool_partial_kernel(const float* __restrict__ x, float* __restrict__ pp) {
    int b = blockIdx.x;
    int chunk = blockIdx.y;
    int d = threadIdx.x;
    float s = 0.f;
    for (int s0 = 0; s0 < 256; s0++) {
        int srow = chunk * 256 + s0;
        s += x[((size_t)(b * SS + srow)) * DD + d];
    }
    pp[(b * 16 + chunk) * DD + d] = s;
}
__global__ void pool_final_kernel(const float* __restrict__ pp, float* __restrict__ pooled) {
    int b = blockIdx.x;
    int d = threadIdx.x;
    float s = 0.f;
    #pragma unroll
    for (int c = 0; c < 16; c++) s += pp[(b * 16 + c) * DD + d];
    pooled[b * DD + d] = s * (1.0f / SS);
}

// ---------------- projection head ----------------
__global__ void head1_kernel(const float* __restrict__ pooled,
                             const float* __restrict__ w, const float* __restrict__ bias,
                             float* __restrict__ h1) {
    int m = blockIdx.y;
    int n = blockIdx.x * 256 + threadIdx.x;
    float s = bias[n];
    for (int k = 0; k < DD; k++) s += pooled[m * DD + k] * w[k * 512 + n];
    const float alpha = 1.6732632423543772f;
    const float scale = 1.0507009873554805f;
    h1[m * 512 + n] = (s > 0.f) ? scale * s : scale * alpha * expm1f(s);
}
__global__ void head2_kernel(const float* __restrict__ h1,
                             const float* __restrict__ w, const float* __restrict__ bias,
                             float* __restrict__ out) {
    int m = blockIdx.y;
    int n = threadIdx.x;
    float s = bias[n];
    for (int k = 0; k < 512; k++) s += h1[m * 512 + k] * w[k * 256 + n];
    out[m * 256 + n] = s;
}

// ---------------- launch ----------------
extern "C" void kernel_launch(void* const* d_in, const int* in_sizes, int n_in,
                              void* d_out, int out_size) {
    const int*   tokens = (const int*)  d_in[0];
    const int*   amask  = (const int*)  d_in[1];
    const float* we     = (const float*)d_in[2];
    const float* pe     = (const float*)d_in[3];
    const float* te     = (const float*)d_in[4];
    const float* ln_e_w = (const float*)d_in[5];
    const float* ln_e_b = (const float*)d_in[6];
    const float* Wq     = (const float*)d_in[7];
    const float* bq     = (const float*)d_in[8];
    const float* Wk     = (const float*)d_in[9];
    const float* bk     = (const float*)d_in[10];
    const float* Wv     = (const float*)d_in[11];
    const float* bv     = (const float*)d_in[12];
    const float* Wo     = (const float*)d_in[13];
    const float* bo     = (const float*)d_in[14];
    const float* ln1_w  = (const float*)d_in[15];
    const float* ln1_b  = (const float*)d_in[16];
    const float* Wi     = (const float*)d_in[17];
    const float* bi     = (const float*)d_in[18];
    const float* Wf     = (const float*)d_in[19];
    const float* bf     = (const float*)d_in[20];
    const float* ln2_w  = (const float*)d_in[21];
    const float* ln2_b  = (const float*)d_in[22];
    const float* p1_w   = (const float*)d_in[23];
    const float* p1_b   = (const float*)d_in[24];
    const float* p2_w   = (const float*)d_in[25];
    const float* p2_b   = (const float*)d_in[26];
    float* out = (float*)d_out;

    float  *px, *pa0, *pa1, *pz, *ppp, *ppool, *ph1;
    __half *pxh, *pqh, *pkh, *pvh, *pch, *phh;
    __half *pwq, *pwk, *pwv, *pwo, *pwi, *pwf;
    cudaGetSymbolAddress((void**)&px, g_x);
    cudaGetSymbolAddress((void**)&pxh, g_xh);
    cudaGetSymbolAddress((void**)&pqh, g_qh);
    cudaGetSymbolAddress((void**)&pkh, g_kh);
    cudaGetSymbolAddress((void**)&pvh, g_vh);
    cudaGetSymbolAddress((void**)&pch, g_ch);
    cudaGetSymbolAddress((void**)&pa0, g_a0);
    cudaGetSymbolAddress((void**)&pa1, g_a1);
    cudaGetSymbolAddress((void**)&pz, g_zero);
    cudaGetSymbolAddress((void**)&phh, g_hh);
    cudaGetSymbolAddress((void**)&ppp, g_pp);
    cudaGetSymbolAddress((void**)&ppool, g_pooled);
    cudaGetSymbolAddress((void**)&ph1, g_h1);
    cudaGetSymbolAddress((void**)&pwq, g_wqh);
    cudaGetSymbolAddress((void**)&pwk, g_wkh);
    cudaGetSymbolAddress((void**)&pwv, g_wvh);
    cudaGetSymbolAddress((void**)&pwo, g_woh);
    cudaGetSymbolAddress((void**)&pwi, g_wih);
    cudaGetSymbolAddress((void**)&pwf, g_wfh);

    cudaFuncSetAttribute(hgemm_kernel,
                         cudaFuncAttributeMaxDynamicSharedMemorySize, TGEMM_SMEM);
    cudaFuncSetAttribute(attn_wmma_kernel,
                         cudaFuncAttributeMaxDynamicSharedMemorySize, ATT_SMEM);

    {
        const int nQ = LL * DD * DD / 4;
        const int nF = LL * DD * FFF / 4;
        convert_h_kernel<<<2048, 256>>>(Wq, pwq, nQ);
        convert_h_kernel<<<2048, 256>>>(Wk, pwk, nQ);
        convert_h_kernel<<<2048, 256>>>(Wv, pwv, nQ);
        convert_h_kernel<<<2048, 256>>>(Wo, pwo, nQ);
        convert_h_kernel<<<4096, 256>>>(Wi, pwi, nF);
        convert_h_kernel<<<4096, 256>>>(Wf, pwf, nF);
    }

    embed_ln_kernel<<<ROWS, 192>>>(tokens, we, pe, te, ln_e_w, ln_e_b, px, pxh);

    dim3 gQKV(DD / 128, ROWS / 128, 3);      // 1152 blocks
    dim3 gSplit(DD / 128, ROWS / 128, 2);    // 768 blocks (split-K O / FF2)
    dim3 gFF1(FFF / 128, ROWS / 128, 1);     // 1536 blocks
    dim3 gAttn(SS / 128, HH, BB);            // 768 blocks

    for (int l = 0; l < LL; l++) {
        const __half* wq = pwq + (size_t)l * DD * DD;
        const __half* wk = pwk + (size_t)l * DD * DD;
        const __half* wv = pwv + (size_t)l * DD * DD;
        const __half* wo = pwo + (size_t)l * DD * DD;
        const __half* wi = pwi + (size_t)l * DD * FFF;
        const __half* wf = pwf + (size_t)l * FFF * DD;

        // fused QKV: full K, no A offset
        hgemm_kernel<<<gQKV, 256, TGEMM_SMEM>>>(
            pxh, DD, 0, 0, wq, wk, wv,
            bq + l * DD, bk + l * DD, bv + l * DD,
            pqh, pkh, pvh, ROWS, DD, DD, 1);

        attn_wmma_kernel<<<gAttn, 256, ATT_SMEM>>>(pqh, pkh, pvh, amask, pch);

        // O projection, split-K2 (Kloop = 384 = 6 x BK)
        hgemm_kernel<<<gSplit, 256, TGEMM_SMEM>>>(
            pch, DD, 384, 0, wo, wo + (size_t)384 * DD, wo,
            bo + l * DD, pz, pz,
            pa0, pa1, pa0, ROWS, DD, 384, 0);
        add_ln_kernel<<<ROWS, 192>>>(px, pa0, pa1, ln1_w + l * DD, ln1_b + l * DD, pxh);

        hgemm_kernel<<<gFF1, 256, TGEMM_SMEM>>>(
            pxh, DD, 0, 0, wi, wi, wi,
            bi + l * FFF, bi + l * FFF, bi + l * FFF,
            phh, phh, phh, ROWS, FFF, DD, 2);

        // FF2, split-K2 (Kloop = 1536 = 24 x BK)
        hgemm_kernel<<<gSplit, 256, TGEMM_SMEM>>>(
            phh, FFF, 1536, 0, wf, wf + (size_t)1536 * DD, wf,
            bf + l * DD, pz, pz,
            pa0, pa1, pa0, ROWS, DD, 1536, 0);
        add_ln_kernel<<<ROWS, 192>>>(px, pa0, pa1, ln2_w + l * DD, ln2_b + l * DD, pxh);
    }

    pool_partial_kernel<<<dim3(BB, 16), DD>>>(px, ppp);
    pool_final_kernel<<<BB, DD>>>(ppp, ppool);
    head1_kernel<<<dim3(2, BB), 256>>>(ppool, p1_w, p1_b, ph1);
    head2_kernel<<<dim3(1, BB), 256>>>(ph1, p2_w, p2_b, out);
}

// round 17
// speedup vs baseline: 1.0560x; 1.0280x over previous
#include <cuda_runtime.h>
#include <cuda_fp16.h>
#include <mma.h>
#include <math.h>
#include <cstdint>

using namespace nvcuda;

// Problem dims
#define BB 2
#define SS 4096
#define DD 768
#define HH 12
#define DHH 64
#define LL 12
#define FFF 3072
#define WW 256
#define ROWS (BB * SS)

typedef unsigned long long ull;

// -------- scratch (device globals; no allocation allowed) --------
__device__ float  g_x [ROWS * DD];
__device__ __half g_xh[ROWS * DD];
__device__ __half g_qh[ROWS * DD];
__device__ __half g_kh[ROWS * DD];
__device__ __half g_vh[ROWS * DD];
__device__ __half g_ch[ROWS * DD];
__device__ float  g_a0[ROWS * DD];
__device__ float  g_a1[ROWS * DD];
__device__ __half g_hh[ROWS * FFF];
__device__ float  g_zero[FFF];
__device__ float  g_pp[BB * 16 * DD];
__device__ float  g_pooled[BB * DD];
__device__ float  g_h1[BB * 512];
__device__ __half g_wqh[LL * DD * DD];
__device__ __half g_wkh[LL * DD * DD];
__device__ __half g_wvh[LL * DD * DD];
__device__ __half g_woh[LL * DD * DD];
__device__ __half g_wih[LL * DD * FFF];
__device__ __half g_wfh[LL * FFF * DD];

// ---------------- cp.async ----------------
__device__ __forceinline__ void cp16(void* dst, const void* src) {
    unsigned int d = (unsigned int)__cvta_generic_to_shared(dst);
    asm volatile("cp.async.cg.shared.global [%0], [%1], 16;" :: "r"(d), "l"(src));
}
#define CP_COMMIT() asm volatile("cp.async.commit_group;")
#define CP_WAIT2()  asm volatile("cp.async.wait_group 2;")
#define CP_WAIT0()  asm volatile("cp.async.wait_group 0;")

// ---------------- ldmatrix / mma PTX ----------------
__device__ __forceinline__ void ldsm4(uint32_t* r, uint32_t addr) {
    asm volatile("ldmatrix.sync.aligned.m8n8.x4.shared.b16 {%0,%1,%2,%3}, [%4];"
                 : "=r"(r[0]), "=r"(r[1]), "=r"(r[2]), "=r"(r[3]) : "r"(addr));
}
__device__ __forceinline__ void ldsm4t(uint32_t* r, uint32_t addr) {
    asm volatile("ldmatrix.sync.aligned.m8n8.x4.trans.shared.b16 {%0,%1,%2,%3}, [%4];"
                 : "=r"(r[0]), "=r"(r[1]), "=r"(r[2]), "=r"(r[3]) : "r"(addr));
}
__device__ __forceinline__ void mma16816(float* c, const uint32_t* a,
                                         uint32_t b0, uint32_t b1) {
    asm volatile("mma.sync.aligned.m16n8k16.row.col.f32.f16.f16.f32 "
                 "{%0,%1,%2,%3}, {%4,%5,%6,%7}, {%8,%9}, {%0,%1,%2,%3};"
                 : "+f"(c[0]), "+f"(c[1]), "+f"(c[2]), "+f"(c[3])
                 : "r"(a[0]), "r"(a[1]), "r"(a[2]), "r"(a[3]), "r"(b0), "r"(b1));
}

// ---------------- misc ----------------
__device__ __forceinline__ float gelu_f(float x) {
    float x3 = x * x * x;
    float t = tanhf(0.7978845608028654f * (x + 0.044715f * x3));
    return 0.5f * x * (1.0f + t);
}
__device__ __forceinline__ float block_reduce_192(float v, float* red) {
    #pragma unroll
    for (int o = 16; o > 0; o >>= 1) v += __shfl_xor_sync(0xffffffffu, v, o);
    __syncthreads();
    if ((threadIdx.x & 31) == 0) red[threadIdx.x >> 5] = v;
    __syncthreads();
    if (threadIdx.x == 0) {
        float s = 0.f;
        #pragma unroll
        for (int i = 0; i < 6; i++) s += red[i];
        red[7] = s;
    }
    __syncthreads();
    return red[7];
}

// ---------------- weight fp32 -> fp16 convert ----------------
__global__ void convert_h_kernel(const float* __restrict__ src, __half* __restrict__ dst,
                                 int n4) {
    int i = blockIdx.x * blockDim.x + threadIdx.x;
    int stride = gridDim.x * blockDim.x;
    for (; i < n4; i += stride) {
        float4 v = ((const float4*)src)[i];
        ((__half2*)dst)[2 * i]     = __floats2half2_rn(v.x, v.y);
        ((__half2*)dst)[2 * i + 1] = __floats2half2_rn(v.z, v.w);
    }
}

// ---------------- embedding + LN ----------------
__global__ __launch_bounds__(192) void embed_ln_kernel(
    const int* __restrict__ tokens,
    const float* __restrict__ we, const float* __restrict__ pe,
    const float* __restrict__ te,
    const float* __restrict__ w, const float* __restrict__ b,
    float* __restrict__ x, __half* __restrict__ xh)
{
    __shared__ float red[8];
    int r = blockIdx.x;
    int ss = r % SS;
    int tok = tokens[r];
    int d4 = threadIdx.x * 4;
    size_t base = (size_t)r * DD;

    float4 wv = *(const float4*)(we + (size_t)tok * DD + d4);
    float4 pv = *(const float4*)(pe + (size_t)ss * DD + d4);
    float4 tv = *(const float4*)(te + d4);
    float f0 = wv.x + pv.x + tv.x;
    float f1 = wv.y + pv.y + tv.y;
    float f2 = wv.z + pv.z + tv.z;
    float f3 = wv.w + pv.w + tv.w;

    float mean = block_reduce_192(f0 + f1 + f2 + f3, red) * (1.0f / DD);
    float e0 = f0 - mean, e1 = f1 - mean, e2 = f2 - mean, e3 = f3 - mean;
    float var = block_reduce_192(e0 * e0 + e1 * e1 + e2 * e2 + e3 * e3, red) * (1.0f / DD);
    float rstd = rsqrtf(var + 1e-5f);

    float4 wt = *(const float4*)(w + d4);
    float4 bt = *(const float4*)(b + d4);
    float o0 = e0 * rstd * wt.x + bt.x;
    float o1 = e1 * rstd * wt.y + bt.y;
    float o2 = e2 * rstd * wt.z + bt.z;
    float o3 = e3 * rstd * wt.w + bt.w;
    *(float4*)(x + base + d4) = make_float4(o0, o1, o2, o3);
    __half2* xo = (__half2*)(xh + base + d4);
    xo[0] = __floats2half2_rn(o0, o1);
    xo[1] = __floats2half2_rn(o2, o3);
}

// ---------------- residual add (two partials) + LN ----------------
__global__ __launch_bounds__(192) void add_ln_kernel(
    float* __restrict__ x, const float* __restrict__ a0, const float* __restrict__ a1,
    const float* __restrict__ w, const float* __restrict__ b,
    __half* __restrict__ xh)
{
    __shared__ float red[8];
    int r = blockIdx.x;
    int d4 = threadIdx.x * 4;
    size_t base = (size_t)r * DD;

    float4 xv = *(const float4*)(x + base + d4);
    float4 v0 = *(const float4*)(a0 + base + d4);
    float4 v1 = *(const float4*)(a1 + base + d4);
    float f0 = xv.x + v0.x + v1.x;
    float f1 = xv.y + v0.y + v1.y;
    float f2 = xv.z + v0.z + v1.z;
    float f3 = xv.w + v0.w + v1.w;

    float mean = block_reduce_192(f0 + f1 + f2 + f3, red) * (1.0f / DD);
    float e0 = f0 - mean, e1 = f1 - mean, e2 = f2 - mean, e3 = f3 - mean;
    float var = block_reduce_192(e0 * e0 + e1 * e1 + e2 * e2 + e3 * e3, red) * (1.0f / DD);
    float rstd = rsqrtf(var + 1e-5f);

    float4 wt = *(const float4*)(w + d4);
    float4 bt = *(const float4*)(b + d4);
    float o0 = e0 * rstd * wt.x + bt.x;
    float o1 = e1 * rstd * wt.y + bt.y;
    float o2 = e2 * rstd * wt.z + bt.z;
    float o3 = e3 * rstd * wt.w + bt.w;
    *(float4*)(x + base + d4) = make_float4(o0, o1, o2, o3);
    __half2* xo = (__half2*)(xh + base + d4);
    xo[0] = __floats2half2_rn(o0, o1);
    xo[1] = __floats2half2_rn(o2, o3);
}

// ---------------- fp16 tensor-core GEMM (ldmatrix + mma.sync m16n8k16) -----
// CTA tile 128x128, 8 warps 4(M)x2(N), warp tile 32x64. BK=32, 4-stage
// cp.async, 2 CTAs/SM. Fragment loads via LDSM (conflict-free with 80B/272B
// row strides). Bias added in epilogue. Per-z (B,bias,C,A-offset).
#define BM 128
#define BN 128
#define BK 32
#define STAGES 4
#define LDA_S 40     // halves: 80 B rows -> LDSM conflict-free
#define LDB_S 136    // halves: 272 B rows -> LDSM conflict-free

#define SMEM_A_BYTES (STAGES * BM * LDA_S * 2)            // 40960
#define SMEM_B_BYTES (STAGES * BK * LDB_S * 2)            // 34816
#define SMEM_BIAS_BYTES 512
#define TGEMM_SMEM (SMEM_A_BYTES + SMEM_B_BYTES + SMEM_BIAS_BYTES)  // 76288

__global__ __launch_bounds__(256, 2) void hgemm_kernel(
    const __half* __restrict__ A, int ldA, int aoff1, int aoff2,
    const __half* __restrict__ B0, const __half* __restrict__ B1, const __half* __restrict__ B2,
    const float* __restrict__ bias0, const float* __restrict__ bias1, const float* __restrict__ bias2,
    void* C0, void* C1, void* C2,
    int M, int N, int Kloop, int mode)
{
    extern __shared__ char dynsmem[];
    __half (*As)[BM][LDA_S] = (__half (*)[BM][LDA_S])dynsmem;
    __half (*Bs)[BK][LDB_S] = (__half (*)[BK][LDB_S])(dynsmem + SMEM_A_BYTES);
    float* biasS = (float*)(dynsmem + SMEM_A_BYTES + SMEM_B_BYTES);

    const __half* B;
    const float* bias;
    void* C;
    int aoff;
    if (blockIdx.z == 0)      { B = B0; bias = bias0; C = C0; aoff = 0; }
    else if (blockIdx.z == 1) { B = B1; bias = bias1; C = C1; aoff = aoff1; }
    else                      { B = B2; bias = bias2; C = C2; aoff = aoff2; }
    const __half* Az = A + aoff;

    int tid = threadIdx.x;
    int wid = tid >> 5;
    int lane = tid & 31;
    int bm = blockIdx.y * BM;
    int bn = blockIdx.x * BN;
    int warp_m = (wid & 3) * 32;
    int warp_n = (wid >> 2) * 64;

    auto load_tile = [&](int it, int buf) {
        int k0 = it * BK;
        #pragma unroll
        for (int r = 0; r < 2; r++) {
            int e = tid + r * 256;
            int m = e >> 2, c8 = (e & 3) * 8;
            cp16(&As[buf][m][c8], Az + (size_t)(bm + m) * ldA + k0 + c8);
        }
        #pragma unroll
        for (int r = 0; r < 2; r++) {
            int e = tid + r * 256;
            int k = e >> 4, c8 = (e & 15) * 8;
            cp16(&Bs[buf][k][c8], B + (size_t)(k0 + k) * N + bn + c8);
        }
    };

    #pragma unroll
    for (int s = 0; s < STAGES - 1; s++) {
        load_tile(s, s);
        CP_COMMIT();
    }

    if (tid < 128) biasS[tid] = bias[bn + tid];

    // lane-derived LDSM address components
    int lrow = lane & 15;           // row within 16
    int lcol8 = (lane >> 4) * 8;    // 0 or 8
    uint32_t asBase = (uint32_t)__cvta_generic_to_shared(&As[0][0][0]);
    uint32_t bsBase = (uint32_t)__cvta_generic_to_shared(&Bs[0][0][0]);

    // accumulators: c[i][jj][0..3], i = m16 block, jj = n8 block (0..7)
    // thread mapping (m16n8): c0:(row=lane>>2, col=2*(lane&3)) c1:(+0,+1)
    //                         c2:(row+8, col)                  c3:(row+8,+1)
    float c[2][8][4];
    #pragma unroll
    for (int i = 0; i < 2; i++)
        #pragma unroll
        for (int j = 0; j < 8; j++)
            #pragma unroll
            for (int t = 0; t < 4; t++) c[i][j][t] = 0.f;

    __syncthreads();

    int NT = Kloop / BK;
    for (int it = 0; it < NT; it++) {
        int buf = it & (STAGES - 1);
        CP_WAIT2();
        __syncthreads();

        uint32_t aBuf = asBase + (uint32_t)buf * (BM * LDA_S * 2);
        uint32_t bBuf = bsBase + (uint32_t)buf * (BK * LDB_S * 2);

        #pragma unroll
        for (int ks = 0; ks < 2; ks++) {
            uint32_t a[2][4];
            #pragma unroll
            for (int i = 0; i < 2; i++)
                ldsm4(a[i], aBuf +
                      ((uint32_t)(warp_m + i * 16 + lrow) * LDA_S + ks * 16 + lcol8) * 2);
            uint32_t b[4][4];
            #pragma unroll
            for (int j = 0; j < 4; j++)
                ldsm4t(b[j], bBuf +
                       ((uint32_t)(ks * 16 + lrow) * LDB_S + warp_n + j * 16 + lcol8) * 2);
            #pragma unroll
            for (int i = 0; i < 2; i++)
                #pragma unroll
                for (int j = 0; j < 4; j++) {
                    mma16816(c[i][2 * j],     a[i], b[j][0], b[j][1]);
                    mma16816(c[i][2 * j + 1], a[i], b[j][2], b[j][3]);
                }
        }

        if (it + STAGES - 1 < NT)
            load_tile(it + STAGES - 1, (it + STAGES - 1) & (STAGES - 1));
        CP_COMMIT();
    }

    // epilogue
    int rloc = lane >> 2;          // 0..7
    int cbase = (lane & 3) * 2;    // 0,2,4,6
    if (mode == 0) {
        float* Cf = (float*)C;
        #pragma unroll
        for (int i = 0; i < 2; i++) {
            int row = bm + warp_m + i * 16 + rloc;
            #pragma unroll
            for (int jj = 0; jj < 8; jj++) {
                int col = warp_n + jj * 8 + cbase;
                float b0 = biasS[col], b1 = biasS[col + 1];
                float2 v0 = make_float2(c[i][jj][0] + b0, c[i][jj][1] + b1);
                float2 v1 = make_float2(c[i][jj][2] + b0, c[i][jj][3] + b1);
                *(float2*)(Cf + (size_t)row * N + bn + col) = v0;
                *(float2*)(Cf + (size_t)(row + 8) * N + bn + col) = v1;
            }
        }
    } else {
        __half* Ch = (__half*)C;
        #pragma unroll
        for (int i = 0; i < 2; i++) {
            int row = bm + warp_m + i * 16 + rloc;
            #pragma unroll
            for (int jj = 0; jj < 8; jj++) {
                int col = warp_n + jj * 8 + cbase;
                float b0 = biasS[col], b1 = biasS[col + 1];
                float v0 = c[i][jj][0] + b0, v1 = c[i][jj][1] + b1;
                float v2 = c[i][jj][2] + b0, v3 = c[i][jj][3] + b1;
                if (mode == 2) {
                    v0 = gelu_f(v0); v1 = gelu_f(v1);
                    v2 = gelu_f(v2); v3 = gelu_f(v3);
                }
                *(__half2*)(Ch + (size_t)row * N + bn + col) = __floats2half2_rn(v0, v1);
                *(__half2*)(Ch + (size_t)(row + 8) * N + bn + col) = __floats2half2_rn(v2, v3);
            }
        }
    }
}

// ---------------- tensor-core local attention ----------------
#define ATT_Q_OFF 0
#define ATT_K_OFF 18432
#define ATT_V_OFF 27648
#define ATT_P_OFF 36864
#define ATT_S_OFF 55296
#define ATT_M_OFF 92160
#define ATT_SMEM  92416

__global__ __launch_bounds__(256, 2) void attn_wmma_kernel(
    const __half* __restrict__ Q, const __half* __restrict__ K,
    const __half* __restrict__ V, const int* __restrict__ mask,
    __half* __restrict__ O)
{
    extern __shared__ char sm[];
    __half* Qs = (__half*)(sm + ATT_Q_OFF);
    __half* Ks = (__half*)(sm + ATT_K_OFF);
    __half* Vs = (__half*)(sm + ATT_V_OFF);
    __half* Ps = (__half*)(sm + ATT_P_OFF);
    float*  Ss = (float*)(sm + ATT_S_OFF);
    int*    Ms = (int*)(sm + ATT_M_OFF);

    int h = blockIdx.y, b = blockIdx.z;
    int tid = threadIdx.x, wid = tid >> 5;
    int q0 = blockIdx.x * 128;
    size_t bS = (size_t)b * SS;

    for (int e = tid; e < 128 * 8; e += 256) {
        int r = e >> 3, c16 = e & 7;
        cp16(Qs + r * 72 + c16 * 8, Q + (bS + q0 + r) * DD + h * DHH + c16 * 8);
    }
    CP_COMMIT();

    float lsum = 0.f;
    int sr = tid >> 1;
    int sc0 = (tid & 1) * 32;

    wmma::fragment<wmma::accumulator, 16, 16, 16, float> co[4];
    #pragma unroll
    for (int j = 0; j < 4; j++) wmma::fill_fragment(co[j], 0.f);

    for (int t = 0; t < 10; t++) {
        __syncthreads();
        int kbase = q0 - 256 + t * 64;
        #pragma unroll
        for (int rr = 0; rr < 2; rr++) {
            int e = tid + rr * 256;
            int row = e >> 3, c16 = e & 7;
            int p = kbase + row;
            if ((unsigned)p < SS) {
                size_t off = (bS + p) * DD + h * DHH + c16 * 8;
                cp16(Ks + row * 72 + c16 * 8, K + off);
                cp16(Vs + row * 72 + c16 * 8, V + off);
            } else {
                *(uint4*)(Ks + row * 72 + c16 * 8) = make_uint4(0, 0, 0, 0);
                *(uint4*)(Vs + row * 72 + c16 * 8) = make_uint4(0, 0, 0, 0);
            }
        }
        if (tid < 64) {
            int p = kbase + tid;
            Ms[tid] = ((unsigned)p < SS) ? mask[b * SS + p] : 0;
        }
        CP_COMMIT();
        CP_WAIT0();
        __syncthreads();

        bool active = (64 * t + 63 >= 16 * wid) && (64 * t <= 527 + 16 * wid);

        if (active) {
            wmma::fragment<wmma::accumulator, 16, 16, 16, float> cs[4];
            #pragma unroll
            for (int j = 0; j < 4; j++) wmma::fill_fragment(cs[j], 0.f);
            #pragma unroll
            for (int kk = 0; kk < 4; kk++) {
                wmma::fragment<wmma::matrix_a, 16, 16, 16, __half, wmma::row_major> a;
                wmma::load_matrix_sync(a, Qs + (16 * wid) * 72 + 16 * kk, 72);
                #pragma unroll
                for (int j = 0; j < 4; j++) {
                    wmma::fragment<wmma::matrix_b, 16, 16, 16, __half, wmma::col_major> bt;
                    wmma::load_matrix_sync(bt, Ks + (16 * j) * 72 + 16 * kk, 72);
                    wmma::mma_sync(cs[j], a, bt, cs[j]);
                }
            }
            #pragma unroll
            for (int j = 0; j < 4; j++)
                wmma::store_matrix_sync(Ss + (16 * wid) * 72 + 16 * j, cs[j], 72,
                                        wmma::mem_row_major);
        }
        __syncthreads();

        if (active) {
            #pragma unroll
            for (int k = 0; k < 32; k++) {
                int col = sc0 + k;
                int d = 64 * t + col - sr;
                float pv = 0.f;
                if (d >= 0 && d <= 512 && Ms[col])
                    pv = __expf(Ss[sr * 72 + col] * 0.125f);
                Ps[sr * 72 + col] = __float2half(pv);
                lsum += pv;
            }
        }
        __syncthreads();

        if (active) {
            #pragma unroll
            for (int kk = 0; kk < 4; kk++) {
                wmma::fragment<wmma::matrix_a, 16, 16, 16, __half, wmma::row_major> a;
                wmma::load_matrix_sync(a, Ps + (16 * wid) * 72 + 16 * kk, 72);
                #pragma unroll
                for (int j = 0; j < 4; j++) {
                    wmma::fragment<wmma::matrix_b, 16, 16, 16, __half, wmma::row_major> bt;
                    wmma::load_matrix_sync(bt, Vs + (16 * kk) * 72 + 16 * j, 72);
                    wmma::mma_sync(co[j], a, bt, co[j]);
                }
            }
        }
    }

    __syncthreads();
    #pragma unroll
    for (int j = 0; j < 4; j++)
        wmma::store_matrix_sync(Ss + (16 * wid) * 72 + 16 * j, co[j], 72,
                                wmma::mem_row_major);
    __syncthreads();

    float ltot = lsum + __shfl_xor_sync(0xffffffff, lsum, 1);
    float inv = 1.0f / ltot;
    __half2* op = (__half2*)(O + (bS + q0 + sr) * DD + h * DHH + sc0);
    #pragma unroll
    for (int k = 0; k < 32; k += 2) {
        float v0 = Ss[sr * 72 + sc0 + k] * inv;
        float v1 = Ss[sr * 72 + sc0 + k + 1] * inv;
        op[k >> 1] = __floats2half2_rn(v0, v1);
    }
}

// ---------------- mean pool ----------------
__global__ void pool_partial_kernel(const float* __restrict__ x, float* __restrict__ pp) {
    int b = blockIdx.x;
    int chunk = blockIdx.y;
    int d = threadIdx.x;
    float s = 0.f;
    for (int s0 = 0; s0 < 256; s0++) {
        int srow = chunk * 256 + s0;
        s += x[((size_t)(b * SS + srow)) * DD + d];
    }
    pp[(b * 16 + chunk) * DD + d] = s;
}
__global__ void pool_final_kernel(const float* __restrict__ pp, float* __restrict__ pooled) {
    int b = blockIdx.x;
    int d = threadIdx.x;
    float s = 0.f;
    #pragma unroll
    for (int c = 0; c < 16; c++) s += pp[(b * 16 + c) * DD + d];
    pooled[b * DD + d] = s * (1.0f / SS);
}

// ---------------- projection head ----------------
__global__ void head1_kernel(const float* __restrict__ pooled,
                             const float* __restrict__ w, const float* __restrict__ bias,
                             float* __restrict__ h1) {
    int m = blockIdx.y;
    int n = blockIdx.x * 256 + threadIdx.x;
    float s = bias[n];
    for (int k = 0; k < DD; k++) s += pooled[m * DD + k] * w[k * 512 + n];
    const float alpha = 1.6732632423543772f;
    const float scale = 1.0507009873554805f;
    h1[m * 512 + n] = (s > 0.f) ? scale * s : scale * alpha * expm1f(s);
}
__global__ void head2_kernel(const float* __restrict__ h1,
                             const float* __restrict__ w, const float* __restrict__ bias,
                             float* __restrict__ out) {
    int m = blockIdx.y;
    int n = threadIdx.x;
    float s = bias[n];
    for (int k = 0; k < 512; k++) s += h1[m * 512 + k] * w[k * 256 + n];
    out[m * 256 + n] = s;
}

// ---------------- launch ----------------
extern "C" void kernel_launch(void* const* d_in, const int* in_sizes, int n_in,
                              void* d_out, int out_size) {
    const int*   tokens = (const int*)  d_in[0];
    const int*   amask  = (const int*)  d_in[1];
    const float* we     = (const float*)d_in[2];
    const float* pe     = (const float*)d_in[3];
    const float* te     = (const float*)d_in[4];
    const float* ln_e_w = (const float*)d_in[5];
    const float* ln_e_b = (const float*)d_in[6];
    const float* Wq     = (const float*)d_in[7];
    const float* bq     = (const float*)d_in[8];
    const float* Wk     = (const float*)d_in[9];
    const float* bk     = (const float*)d_in[10];
    const float* Wv     = (const float*)d_in[11];
    const float* bv     = (const float*)d_in[12];
    const float* Wo     = (const float*)d_in[13];
    const float* bo     = (const float*)d_in[14];
    const float* ln1_w  = (const float*)d_in[15];
    const float* ln1_b  = (const float*)d_in[16];
    const float* Wi     = (const float*)d_in[17];
    const float* bi     = (const float*)d_in[18];
    const float* Wf     = (const float*)d_in[19];
    const float* bf     = (const float*)d_in[20];
    const float* ln2_w  = (const float*)d_in[21];
    const float* ln2_b  = (const float*)d_in[22];
    const float* p1_w   = (const float*)d_in[23];
    const float* p1_b   = (const float*)d_in[24];
    const float* p2_w   = (const float*)d_in[25];
    const float* p2_b   = (const float*)d_in[26];
    float* out = (float*)d_out;

    float  *px, *pa0, *pa1, *pz, *ppp, *ppool, *ph1;
    __half *pxh, *pqh, *pkh, *pvh, *pch, *phh;
    __half *pwq, *pwk, *pwv, *pwo, *pwi, *pwf;
    cudaGetSymbolAddress((void**)&px, g_x);
    cudaGetSymbolAddress((void**)&pxh, g_xh);
    cudaGetSymbolAddress((void**)&pqh, g_qh);
    cudaGetSymbolAddress((void**)&pkh, g_kh);
    cudaGetSymbolAddress((void**)&pvh, g_vh);
    cudaGetSymbolAddress((void**)&pch, g_ch);
    cudaGetSymbolAddress((void**)&pa0, g_a0);
    cudaGetSymbolAddress((void**)&pa1, g_a1);
    cudaGetSymbolAddress((void**)&pz, g_zero);
    cudaGetSymbolAddress((void**)&phh, g_hh);
    cudaGetSymbolAddress((void**)&ppp, g_pp);
    cudaGetSymbolAddress((void**)&ppool, g_pooled);
    cudaGetSymbolAddress((void**)&ph1, g_h1);
    cudaGetSymbolAddress((void**)&pwq, g_wqh);
    cudaGetSymbolAddress((void**)&pwk, g_wkh);
    cudaGetSymbolAddress((void**)&pwv, g_wvh);
    cudaGetSymbolAddress((void**)&pwo, g_woh);
    cudaGetSymbolAddress((void**)&pwi, g_wih);
    cudaGetSymbolAddress((void**)&pwf, g_wfh);

    cudaFuncSetAttribute(hgemm_kernel,
                         cudaFuncAttributeMaxDynamicSharedMemorySize, TGEMM_SMEM);
    cudaFuncSetAttribute(attn_wmma_kernel,
                         cudaFuncAttributeMaxDynamicSharedMemorySize, ATT_SMEM);

    {
        const int nQ = LL * DD * DD / 4;
        const int nF = LL * DD * FFF / 4;
        convert_h_kernel<<<2048, 256>>>(Wq, pwq, nQ);
        convert_h_kernel<<<2048, 256>>>(Wk, pwk, nQ);
        convert_h_kernel<<<2048, 256>>>(Wv, pwv, nQ);
        convert_h_kernel<<<2048, 256>>>(Wo, pwo, nQ);
        convert_h_kernel<<<4096, 256>>>(Wi, pwi, nF);
        convert_h_kernel<<<4096, 256>>>(Wf, pwf, nF);
    }

    embed_ln_kernel<<<ROWS, 192>>>(tokens, we, pe, te, ln_e_w, ln_e_b, px, pxh);

    dim3 gQKV(DD / 128, ROWS / 128, 3);      // 1152 blocks
    dim3 gSplit(DD / 128, ROWS / 128, 2);    // 768 blocks
    dim3 gFF1(FFF / 128, ROWS / 128, 1);     // 1536 blocks
    dim3 gAttn(SS / 128, HH, BB);            // 768 blocks

    for (int l = 0; l < LL; l++) {
        const __half* wq = pwq + (size_t)l * DD * DD;
        const __half* wk = pwk + (size_t)l * DD * DD;
        const __half* wv = pwv + (size_t)l * DD * DD;
        const __half* wo = pwo + (size_t)l * DD * DD;
        const __half* wi = pwi + (size_t)l * DD * FFF;
        const __half* wf = pwf + (size_t)l * FFF * DD;

        hgemm_kernel<<<gQKV, 256, TGEMM_SMEM>>>(
            pxh, DD, 0, 0, wq, wk, wv,
            bq + l * DD, bk + l * DD, bv + l * DD,
            pqh, pkh, pvh, ROWS, DD, DD, 1);

        attn_wmma_kernel<<<gAttn, 256, ATT_SMEM>>>(pqh, pkh, pvh, amask, pch);

        hgemm_kernel<<<gSplit, 256, TGEMM_SMEM>>>(
            pch, DD, 384, 0, wo, wo + (size_t)384 * DD, wo,
            bo + l * DD, pz, pz,
            pa0, pa1, pa0, ROWS, DD, 384, 0);
        add_ln_kernel<<<ROWS, 192>>>(px, pa0, pa1, ln1_w + l * DD, ln1_b + l * DD, pxh);

        hgemm_kernel<<<gFF1, 256, TGEMM_SMEM>>>(
            pxh, DD, 0, 0, wi, wi, wi,
            bi + l * FFF, bi + l * FFF, bi + l * FFF,
            phh, phh, phh, ROWS, FFF, DD, 2);

        hgemm_kernel<<<gSplit, 256, TGEMM_SMEM>>>(
            phh, FFF, 1536, 0, wf, wf + (size_t)1536 * DD, wf,
            bf + l * DD, pz, pz,
            pa0, pa1, pa0, ROWS, DD, 1536, 0);
        add_ln_kernel<<<ROWS, 192>>>(px, pa0, pa1, ln2_w + l * DD, ln2_b + l * DD, pxh);
    }

    pool_partial_kernel<<<dim3(BB, 16), DD>>>(px, ppp);
    pool_final_kernel<<<BB, DD>>>(ppp, ppool);
    head1_kernel<<<dim3(2, BB), 256>>>(ppool, p1_w, p1_b, ph1);
    head2_kernel<<<dim3(1, BB), 256>>>(ph1, p2_w, p2_b, out);
}